// round 9
// baseline (speedup 1.0000x reference)
#include <cuda_runtime.h>
#include <cuda_fp16.h>
#include <cstdint>

#define C_IN   128
#define C_OUT  256
#define TAPS   4
#define N_MAX  262144
#define PADN_MAX (N_MAX + TAPS * 128)
#define BN_EPS 1e-4f
#define PIT    36                  // smem pitch in floats (conflict-free)
#define ASTAGE (128 * PIT)         // floats per buffer (A or B chunk)

// ---------------- device scratch ----------------
__device__ __half g_scratch[(size_t)PADN_MAX * C_OUT];  // contributions, fp16, perm order
__device__ int   g_pslot[N_MAX * TAPS];                 // pslot[site*4+tap] = perm position or -1
__device__ int   g_perm[PADN_MAX];                      // perm position -> input row
__device__ float g_Bt[TAPS * C_OUT * C_IN];             // W as [tap][n][k-pair-permuted], tf32
__device__ int   g_tap_count[TAPS];
__device__ int   g_pad_base[TAPS + 1];
__device__ int   g_tap_cursor[TAPS];
__device__ int   g_ctr;                                 // prep completion counter
__device__ float g_sum[C_OUT];
__device__ float g_sumsq[C_OUT];
__device__ float g_cnt;
__device__ float g_scale[C_OUT];
__device__ float g_bias[C_OUT];

// ---------------- helpers ----------------
__device__ __forceinline__ uint32_t smem_u32(const void* p) {
    uint32_t a;
    asm("{ .reg .u64 t; cvta.to.shared.u64 t, %1; cvt.u32.u64 %0, t; }" : "=r"(a) : "l"(p));
    return a;
}
__device__ __forceinline__ uint32_t f2tf32(float f) {
    uint32_t r;
    asm("cvt.rna.tf32.f32 %0, %1;" : "=r"(r) : "f"(f));
    return r;
}

#define CP_ASYNC(sa, ga, sz) \
    asm volatile("cp.async.cg.shared.global [%0], [%1], 16, %2;" :: "r"(sa), "l"(ga), "r"(sz))
#define CP_COMMIT() asm volatile("cp.async.commit_group;")
#define CP_WAIT(n)  asm volatile("cp.async.wait_group %0;" :: "n"(n))

#define MMA(d, a, b0, b1)                                                          \
    asm volatile("mma.sync.aligned.m16n8k8.row.col.f32.tf32.tf32.f32 "             \
                 "{%0,%1,%2,%3}, {%4,%5,%6,%7}, {%8,%9}, {%0,%1,%2,%3};"           \
                 : "+f"((d)[0]), "+f"((d)[1]), "+f"((d)[2]), "+f"((d)[3])          \
                 : "r"((a)[0]), "r"((a)[1]), "r"((a)[2]), "r"((a)[3]),             \
                   "r"(b0), "r"(b1))

// read 8 channels (four half2) as 8 floats via one 16B load
__device__ __forceinline__ void ld_scratch8(const __half* p, float* v) {
    uint4 u = *(const uint4*)p;
    float2 f0 = __half22float2(*(__half2*)&u.x);
    float2 f1 = __half22float2(*(__half2*)&u.y);
    float2 f2 = __half22float2(*(__half2*)&u.z);
    float2 f3 = __half22float2(*(__half2*)&u.w);
    v[0] = f0.x; v[1] = f0.y; v[2] = f1.x; v[3] = f1.y;
    v[4] = f2.x; v[5] = f2.y; v[6] = f3.x; v[7] = f3.y;
}

// ---------------- K_prep: W transpose+round (k-pair permuted) + pslot init +
//                  tap histogram + last-block prefix ----------------
__global__ void k_prep(const float* __restrict__ W, const int* __restrict__ offset, int N) {
    for (int i = blockIdx.x * blockDim.x + threadIdx.x; i < TAPS * C_IN * C_OUT;
         i += gridDim.x * blockDim.x) {
        int t = i / (C_IN * C_OUT);
        int r = i % (C_IN * C_OUT);
        int k = r >> 8, n = r & 255;
        // pair-permute within each 8-group: (k,k+4) -> adjacent
        int kp = (k & ~7) | ((k & 3) << 1) | ((k >> 2) & 1);
        g_Bt[t * C_OUT * C_IN + n * C_IN + kp] = __uint_as_float(f2tf32(W[i]));
    }
    for (int i = blockIdx.x * blockDim.x + threadIdx.x; i < N * TAPS;
         i += gridDim.x * blockDim.x)
        g_pslot[i] = -1;

    int c0 = 0, c1 = 0, c2 = 0, c3 = 0;
    for (int i = blockIdx.x * blockDim.x + threadIdx.x; i < N;
         i += gridDim.x * blockDim.x) {
        int k = offset[i];
        c0 += (k == 0); c1 += (k == 1); c2 += (k == 2); c3 += (k == 3);
    }
    c0 = __reduce_add_sync(0xffffffffu, c0);
    c1 = __reduce_add_sync(0xffffffffu, c1);
    c2 = __reduce_add_sync(0xffffffffu, c2);
    c3 = __reduce_add_sync(0xffffffffu, c3);
    if ((threadIdx.x & 31) == 0) {
        atomicAdd(&g_tap_count[0], c0);
        atomicAdd(&g_tap_count[1], c1);
        atomicAdd(&g_tap_count[2], c2);
        atomicAdd(&g_tap_count[3], c3);
    }
    __syncthreads();
    if (threadIdx.x == 0) {
        __threadfence();
        int done = atomicAdd(&g_ctr, 1);
        if (done == (int)gridDim.x - 1) {
            g_ctr = 0;                     // reset for next replay
            int b = 0;
            for (int t = 0; t < TAPS; t++) {
                g_pad_base[t]   = b;
                g_tap_cursor[t] = b;
                b += (g_tap_count[t] + 127) & ~127;
            }
            g_pad_base[TAPS] = b;
        }
    }
}

// ---------------- K_perm: permutation + inverse slot map + active count ----------------
__global__ void k_perm(const int* __restrict__ offset, const int* __restrict__ out_index,
                       const float* __restrict__ mask, int N) {
    int lane = threadIdx.x & 31;
    float cm = 0.f;
    for (int i = blockIdx.x * blockDim.x + threadIdx.x; i < N;
         i += gridDim.x * blockDim.x) {
        int k = offset[i];
        unsigned grp = __match_any_sync(0xffffffffu, k);
        int leader   = __ffs(grp) - 1;
        int rank     = __popc(grp & ((1u << lane) - 1u));
        int base = 0;
        if (lane == leader) base = atomicAdd(&g_tap_cursor[k], __popc(grp));
        base = __shfl_sync(0xffffffffu, base, leader);
        int pos = base + rank;
        g_perm[pos] = i;
        g_pslot[(size_t)out_index[i] * TAPS + k] = pos;
        cm += mask[i];
    }
#pragma unroll
    for (int o = 16; o; o >>= 1) cm += __shfl_xor_sync(0xffffffffu, cm, o);
    if ((threadIdx.x & 31) == 0) atomicAdd(&g_cnt, cm);
}

// ---------------- K_conv: per-tap tf32 GEMM -> fp16 scratch, 3-stage cp.async pipeline --
#define SMEM_BYTES ((256 + 6 * ASTAGE) * 4)

__global__ __launch_bounds__(256, 2)
void k_conv(const float* __restrict__ x) {
    extern __shared__ float sm[];
    int*   srow = (int*)sm;                  // 128 ints (+128 pad)
    float* As   = sm + 256;                  // 3 stages of 128 x PIT
    float* Bs   = sm + 256 + 3 * ASTAGE;

    const int tid  = threadIdx.x;
    const int lane = tid & 31;
    const int wid  = tid >> 5;
    const int wm   = wid & 3;
    const int wn   = wid >> 2;
    const int p0   = (int)blockIdx.y * 128;
    if (p0 >= g_pad_base[TAPS]) return;

    int tap = 0;
#pragma unroll
    for (int t = 1; t < TAPS; t++)
        if (p0 >= g_pad_base[t]) tap = t;

    const int colStart = (int)blockIdx.x * 128;
    const float* Bt = g_Bt + (size_t)tap * (C_OUT * C_IN);

    if (tid < 128) srow[tid] = g_perm[p0 + tid];  // pad slots: stale, rows unused downstream
    __syncthreads();

    const uint32_t aBase = smem_u32(As);
    const uint32_t bBase = smem_u32(Bs);

    float acc[2][8][4];
#pragma unroll
    for (int i = 0; i < 2; i++)
#pragma unroll
        for (int j = 0; j < 8; j++)
#pragma unroll
            for (int q = 0; q < 4; q++) acc[i][j][q] = 0.f;

#define LOAD_CHUNK(c)                                                              \
    do {                                                                           \
        const int _k0 = (c) * 32, _st = (c) % 3;                                   \
        uint32_t _sa = aBase + (uint32_t)(_st * ASTAGE) * 4u;                      \
        uint32_t _sb = bBase + (uint32_t)(_st * ASTAGE) * 4u;                      \
        _Pragma("unroll")                                                          \
        for (int _u = 0; _u < 4; _u++) {                                           \
            int _seg = _u * 256 + tid;                                             \
            int _row = _seg >> 3, _q = _seg & 7;                                   \
            int _src = srow[_row];                                                 \
            const float* _ga = x + (size_t)_src * C_IN + _k0 + _q * 4;             \
            CP_ASYNC(_sa + (uint32_t)(_row * PIT + _q * 4) * 4u, _ga, 16);         \
        }                                                                          \
        _Pragma("unroll")                                                          \
        for (int _u = 0; _u < 4; _u++) {                                           \
            int _seg = _u * 256 + tid;                                             \
            int _n = _seg >> 3, _q = _seg & 7;                                     \
            const float* _gb = Bt + (size_t)(colStart + _n) * C_IN + _k0 + _q * 4; \
            CP_ASYNC(_sb + (uint32_t)(_n * PIT + _q * 4) * 4u, _gb, 16);           \
        }                                                                          \
        CP_COMMIT();                                                               \
    } while (0)

#define COMPUTE(c)                                                                 \
    do {                                                                           \
        const float* Ac = As + ((c) % 3) * ASTAGE;                                 \
        const float* Bc = Bs + ((c) % 3) * ASTAGE;                                 \
        _Pragma("unroll")                                                          \
        for (int kk = 0; kk < 4; kk++) {                                           \
            const int k8 = kk * 8;                                                 \
            uint32_t a[2][4];                                                      \
            _Pragma("unroll")                                                      \
            for (int i = 0; i < 2; i++) {                                          \
                const float* ap = Ac + (wm * 32 + i * 16 + (lane >> 2)) * PIT      \
                                  + k8 + (lane & 3);                               \
                a[i][0] = f2tf32(ap[0]);                                           \
                a[i][1] = f2tf32(ap[8 * PIT]);                                     \
                a[i][2] = f2tf32(ap[4]);                                           \
                a[i][3] = f2tf32(ap[8 * PIT + 4]);                                 \
            }                                                                      \
            _Pragma("unroll")                                                      \
            for (int j = 0; j < 8; j++) {                                          \
                const float2 bb = *(const float2*)(Bc +                            \
                    (wn * 64 + j * 8 + (lane >> 2)) * PIT + k8 + (lane & 3) * 2);  \
                uint32_t b0 = __float_as_uint(bb.x);                               \
                uint32_t b1 = __float_as_uint(bb.y);                               \
                MMA(acc[0][j], a[0], b0, b1);                                      \
                MMA(acc[1][j], a[1], b0, b1);                                      \
            }                                                                      \
        }                                                                          \
    } while (0)

    LOAD_CHUNK(0);
    LOAD_CHUNK(1);

    LOAD_CHUNK(2);
    CP_WAIT(2); __syncthreads();
    COMPUTE(0); __syncthreads();          // protects stage 0 before LOAD_CHUNK(3)

    LOAD_CHUNK(3);
    CP_WAIT(2); __syncthreads();
    COMPUTE(1);                            // no smem writes follow: no barrier needed

    CP_WAIT(1); __syncthreads();
    COMPUTE(2);

    CP_WAIT(0); __syncthreads();
    COMPUTE(3);

    // ---- epilogue: fp16 stores at sequential perm positions (coalesced) ----
#pragma unroll
    for (int i = 0; i < 2; i++) {
#pragma unroll
        for (int j = 0; j < 8; j++) {
            int rp = p0 + wm * 32 + i * 16 + (lane >> 2);
            int cg = colStart + wn * 64 + j * 8 + (lane & 3) * 2;
            __half2 h01 = __floats2half2_rn(acc[i][j][0], acc[i][j][1]);
            __half2 h23 = __floats2half2_rn(acc[i][j][2], acc[i][j][3]);
            *(__half2*)&g_scratch[(size_t)rp * C_OUT + cg] = h01;
            *(__half2*)&g_scratch[(size_t)(rp + 8) * C_OUT + cg] = h23;
        }
    }
#undef LOAD_CHUNK
#undef COMPUTE
}

// ---------------- K_cstats: combine (discard) + per-channel stats ----------------
#define SITES_PER_BLOCK 256
__global__ __launch_bounds__(256)
void k_cstats(int N) {
    __shared__ int   sp[SITES_PER_BLOCK * TAPS];   // 4 KB
    __shared__ float ssum[C_OUT], ssq[C_OUT];
    const int tid = threadIdx.x;
    const int s0  = blockIdx.x * SITES_PER_BLOCK;

    for (int i = tid; i < C_OUT; i += 256) { ssum[i] = 0.f; ssq[i] = 0.f; }
    for (int i = tid; i < SITES_PER_BLOCK * TAPS; i += 256) {
        int site = s0 + (i >> 2);
        sp[i] = (site < N) ? g_pslot[(size_t)site * TAPS + (i & 3)] : -1;
    }
    __syncthreads();

    const int c8 = tid & 31, sr = tid >> 5;
    float ls[8], lq[8];
#pragma unroll
    for (int c = 0; c < 8; c++) { ls[c] = 0.f; lq[c] = 0.f; }

    for (int it = 0; it < SITES_PER_BLOCK / 8; it++) {
        int sl = it * 8 + sr;
        float v[8];
#pragma unroll
        for (int c = 0; c < 8; c++) v[c] = 0.f;
#pragma unroll
        for (int t = 0; t < TAPS; t++) {
            int p = sp[sl * 4 + t];
            if (p >= 0) {
                float u[8];
                ld_scratch8(g_scratch + (size_t)p * C_OUT + c8 * 8, u);
#pragma unroll
                for (int c = 0; c < 8; c++) v[c] += u[c];
            }
        }
#pragma unroll
        for (int c = 0; c < 8; c++) { ls[c] += v[c]; lq[c] += v[c] * v[c]; }
    }
#pragma unroll
    for (int c = 0; c < 8; c++) {
        atomicAdd(&ssum[c8 * 8 + c], ls[c]);
        atomicAdd(&ssq[c8 * 8 + c], lq[c]);
    }
    __syncthreads();
    for (int i = tid; i < C_OUT; i += 256) {
        atomicAdd(&g_sum[i], ssum[i]);
        atomicAdd(&g_sumsq[i], ssq[i]);
    }
}

// ---------------- K_bn ----------------
__global__ void k_bn(const float* __restrict__ gamma, const float* __restrict__ beta) {
    int c = threadIdx.x;
    float cnt  = g_cnt;
    float mean = g_sum[c] / cnt;
    float var  = fmaxf(g_sumsq[c] / cnt - mean * mean, 0.f);
    float sc   = rsqrtf(var + BN_EPS) * gamma[c];
    float bi   = beta[c] - mean * sc;
    g_scale[c] = sc;
    g_bias[c]  = bi;
    g_sum[c]   = 0.f;
    g_sumsq[c] = 0.f;
    if (c == 0) g_cnt = 0.f;
    if (c < TAPS) g_tap_count[c] = 0;
}

// ---------------- K_final: recombine + BN + ReLU + mask -> y (single write) ------------
__global__ __launch_bounds__(256)
void k_final(float* __restrict__ y, const float* __restrict__ mask, int N) {
    __shared__ int sp[SITES_PER_BLOCK * TAPS];
    const int tid = threadIdx.x;
    const int s0  = blockIdx.x * SITES_PER_BLOCK;

    for (int i = tid; i < SITES_PER_BLOCK * TAPS; i += 256) {
        int site = s0 + (i >> 2);
        sp[i] = (site < N) ? g_pslot[(size_t)site * TAPS + (i & 3)] : -1;
    }
    __syncthreads();

    const int c8 = tid & 31, sr = tid >> 5;
    float sc[8], bi[8];
    *(float4*)&sc[0] = *(const float4*)&g_scale[c8 * 8];
    *(float4*)&sc[4] = *(const float4*)&g_scale[c8 * 8 + 4];
    *(float4*)&bi[0] = *(const float4*)&g_bias[c8 * 8];
    *(float4*)&bi[4] = *(const float4*)&g_bias[c8 * 8 + 4];

    for (int it = 0; it < SITES_PER_BLOCK / 8; it++) {
        int sl = it * 8 + sr;
        int site = s0 + sl;
        if (site >= N) continue;
        float v[8];
#pragma unroll
        for (int c = 0; c < 8; c++) v[c] = 0.f;
#pragma unroll
        for (int t = 0; t < TAPS; t++) {
            int p = sp[sl * 4 + t];
            if (p >= 0) {
                float u[8];
                ld_scratch8(g_scratch + (size_t)p * C_OUT + c8 * 8, u);
#pragma unroll
                for (int c = 0; c < 8; c++) v[c] += u[c];
            }
        }
        float m = mask[site];
#pragma unroll
        for (int c = 0; c < 8; c++)
            v[c] = fmaxf(fmaf(v[c], sc[c], bi[c]), 0.f) * m;
        float4* o = (float4*)(y + (size_t)site * C_OUT + c8 * 8);
        o[0] = make_float4(v[0], v[1], v[2], v[3]);
        o[1] = make_float4(v[4], v[5], v[6], v[7]);
    }
}

// ---------------- launch ----------------
extern "C" void kernel_launch(void* const* d_in, const int* in_sizes, int n_in,
                              void* d_out, int out_size) {
    const float* x         = (const float*)d_in[0];
    const float* W         = (const float*)d_in[1];
    const float* gamma     = (const float*)d_in[2];
    const float* beta      = (const float*)d_in[3];
    const int*   offset    = (const int*)d_in[4];
    const int*   out_index = (const int*)d_in[5];
    const float* mask      = (const float*)d_in[6];
    float*       out       = (float*)d_out;

    int N = in_sizes[4];
    if (N > N_MAX) N = N_MAX;

    cudaFuncSetAttribute(k_conv, cudaFuncAttributeMaxDynamicSharedMemorySize,
                         SMEM_BYTES);

    k_prep<<<256, 256>>>(W, offset, N);                                     // 0
    k_perm<<<256, 256>>>(offset, out_index, mask, N);                       // 1

    int tiles = (N + 127) / 128 + TAPS;   // upper bound incl. per-tap padding
    k_conv<<<dim3(2, tiles), 256, SMEM_BYTES>>>(x);                         // 2

    int cb = (N + SITES_PER_BLOCK - 1) / SITES_PER_BLOCK;
    k_cstats<<<cb, 256>>>(N);                                               // 3
    k_bn<<<1, 256>>>(gamma, beta);                                          // 4
    k_final<<<cb, 256>>>(out, mask, N);                                     // 5  <- ncu -s 5
}

// round 10
// speedup vs baseline: 1.0239x; 1.0239x over previous
#include <cuda_runtime.h>
#include <cuda_fp16.h>
#include <cstdint>

#define C_IN   128
#define C_OUT  256
#define TAPS   4
#define N_MAX  262144
#define PADN_MAX (N_MAX + TAPS * 128)
#define BN_EPS 1e-4f
#define PIT    36                  // smem pitch in floats (conflict-free)
#define ASTAGE (128 * PIT)         // floats per buffer (A or B chunk)

// ---------------- device scratch ----------------
__device__ __half g_scratch[(size_t)PADN_MAX * C_OUT];  // contributions, fp16, perm order
__device__ int   g_pslot[N_MAX * TAPS];                 // pslot[site*4+tap] = perm position or -1
__device__ int   g_perm[PADN_MAX];                      // perm position -> input row
__device__ float g_Bt[TAPS * C_OUT * C_IN];             // W as [tap][n][k], tf32-rounded
__device__ int   g_tap_count[TAPS];
__device__ int   g_pad_base[TAPS + 1];
__device__ int   g_tap_cursor[TAPS];
__device__ int   g_ctr;                                 // prep completion counter
__device__ float g_sum[C_OUT];
__device__ float g_sumsq[C_OUT];
__device__ float g_cnt;
__device__ float g_scale[C_OUT];
__device__ float g_bias[C_OUT];

// ---------------- helpers ----------------
__device__ __forceinline__ uint32_t smem_u32(const void* p) {
    uint32_t a;
    asm("{ .reg .u64 t; cvta.to.shared.u64 t, %1; cvt.u32.u64 %0, t; }" : "=r"(a) : "l"(p));
    return a;
}
__device__ __forceinline__ uint32_t f2tf32(float f) {
    uint32_t r;
    asm("cvt.rna.tf32.f32 %0, %1;" : "=r"(r) : "f"(f));
    return r;
}

#define CP_ASYNC(sa, ga, sz) \
    asm volatile("cp.async.cg.shared.global [%0], [%1], 16, %2;" :: "r"(sa), "l"(ga), "r"(sz))
#define CP_COMMIT() asm volatile("cp.async.commit_group;")
#define CP_WAIT(n)  asm volatile("cp.async.wait_group %0;" :: "n"(n))

#define MMA(d, a, b0, b1)                                                          \
    asm volatile("mma.sync.aligned.m16n8k8.row.col.f32.tf32.tf32.f32 "             \
                 "{%0,%1,%2,%3}, {%4,%5,%6,%7}, {%8,%9}, {%0,%1,%2,%3};"           \
                 : "+f"((d)[0]), "+f"((d)[1]), "+f"((d)[2]), "+f"((d)[3])          \
                 : "r"((a)[0]), "r"((a)[1]), "r"((a)[2]), "r"((a)[3]),             \
                   "r"(b0), "r"(b1))

// read 8 channels (four half2) as 8 floats via one 16B load
__device__ __forceinline__ void ld_scratch8(const __half* p, float* v) {
    uint4 u = *(const uint4*)p;
    float2 f0 = __half22float2(*(__half2*)&u.x);
    float2 f1 = __half22float2(*(__half2*)&u.y);
    float2 f2 = __half22float2(*(__half2*)&u.z);
    float2 f3 = __half22float2(*(__half2*)&u.w);
    v[0] = f0.x; v[1] = f0.y; v[2] = f1.x; v[3] = f1.y;
    v[4] = f2.x; v[5] = f2.y; v[6] = f3.x; v[7] = f3.y;
}

// ---------------- K_prep: W transpose+round + pslot init + histogram + last-block prefix
__global__ void k_prep(const float* __restrict__ W, const int* __restrict__ offset, int N) {
    for (int i = blockIdx.x * blockDim.x + threadIdx.x; i < TAPS * C_IN * C_OUT;
         i += gridDim.x * blockDim.x) {
        int t = i / (C_IN * C_OUT);
        int r = i % (C_IN * C_OUT);
        int k = r >> 8, n = r & 255;
        g_Bt[t * C_OUT * C_IN + n * C_IN + k] = __uint_as_float(f2tf32(W[i]));
    }
    for (int i = blockIdx.x * blockDim.x + threadIdx.x; i < N * TAPS;
         i += gridDim.x * blockDim.x)
        g_pslot[i] = -1;

    int c0 = 0, c1 = 0, c2 = 0, c3 = 0;
    for (int i = blockIdx.x * blockDim.x + threadIdx.x; i < N;
         i += gridDim.x * blockDim.x) {
        int k = offset[i];
        c0 += (k == 0); c1 += (k == 1); c2 += (k == 2); c3 += (k == 3);
    }
    c0 = __reduce_add_sync(0xffffffffu, c0);
    c1 = __reduce_add_sync(0xffffffffu, c1);
    c2 = __reduce_add_sync(0xffffffffu, c2);
    c3 = __reduce_add_sync(0xffffffffu, c3);
    if ((threadIdx.x & 31) == 0) {
        atomicAdd(&g_tap_count[0], c0);
        atomicAdd(&g_tap_count[1], c1);
        atomicAdd(&g_tap_count[2], c2);
        atomicAdd(&g_tap_count[3], c3);
    }
    __syncthreads();
    if (threadIdx.x == 0) {
        __threadfence();
        int done = atomicAdd(&g_ctr, 1);
        if (done == (int)gridDim.x - 1) {
            g_ctr = 0;                     // reset for next replay
            int b = 0;
            for (int t = 0; t < TAPS; t++) {
                g_pad_base[t]   = b;
                g_tap_cursor[t] = b;
                b += (g_tap_count[t] + 127) & ~127;
            }
            g_pad_base[TAPS] = b;
        }
    }
}

// ---------------- K_perm: permutation + inverse slot map + active count ----------------
__global__ void k_perm(const int* __restrict__ offset, const int* __restrict__ out_index,
                       const float* __restrict__ mask, int N) {
    int lane = threadIdx.x & 31;
    float cm = 0.f;
    for (int i = blockIdx.x * blockDim.x + threadIdx.x; i < N;
         i += gridDim.x * blockDim.x) {
        int k = offset[i];
        unsigned grp = __match_any_sync(0xffffffffu, k);
        int leader   = __ffs(grp) - 1;
        int rank     = __popc(grp & ((1u << lane) - 1u));
        int base = 0;
        if (lane == leader) base = atomicAdd(&g_tap_cursor[k], __popc(grp));
        base = __shfl_sync(0xffffffffu, base, leader);
        int pos = base + rank;
        g_perm[pos] = i;
        g_pslot[(size_t)out_index[i] * TAPS + k] = pos;
        cm += mask[i];
    }
#pragma unroll
    for (int o = 16; o; o >>= 1) cm += __shfl_xor_sync(0xffffffffu, cm, o);
    if ((threadIdx.x & 31) == 0) atomicAdd(&g_cnt, cm);
}

// ---------------- K_conv: per-tap tf32 GEMM -> fp16 scratch, 3-stage cp.async pipeline --
#define SMEM_BYTES ((256 + 6 * ASTAGE) * 4)

__global__ __launch_bounds__(256, 2)
void k_conv(const float* __restrict__ x) {
    extern __shared__ float sm[];
    int*   srow = (int*)sm;                  // 128 ints (+128 pad)
    float* As   = sm + 256;                  // 3 stages of 128 x PIT
    float* Bs   = sm + 256 + 3 * ASTAGE;

    const int tid  = threadIdx.x;
    const int lane = tid & 31;
    const int wid  = tid >> 5;
    const int wm   = wid & 3;
    const int wn   = wid >> 2;
    const int p0   = (int)blockIdx.y * 128;
    if (p0 >= g_pad_base[TAPS]) return;

    int tap = 0;
#pragma unroll
    for (int t = 1; t < TAPS; t++)
        if (p0 >= g_pad_base[t]) tap = t;

    const int colStart = (int)blockIdx.x * 128;
    const float* Bt = g_Bt + (size_t)tap * (C_OUT * C_IN);

    if (tid < 128) srow[tid] = g_perm[p0 + tid];  // pad slots: stale, rows unused downstream
    __syncthreads();

    const uint32_t aBase = smem_u32(As);
    const uint32_t bBase = smem_u32(Bs);

    float acc[2][8][4];
#pragma unroll
    for (int i = 0; i < 2; i++)
#pragma unroll
        for (int j = 0; j < 8; j++)
#pragma unroll
            for (int q = 0; q < 4; q++) acc[i][j][q] = 0.f;

#define LOAD_CHUNK(c)                                                              \
    do {                                                                           \
        const int _k0 = (c) * 32, _st = (c) % 3;                                   \
        uint32_t _sa = aBase + (uint32_t)(_st * ASTAGE) * 4u;                      \
        uint32_t _sb = bBase + (uint32_t)(_st * ASTAGE) * 4u;                      \
        _Pragma("unroll")                                                          \
        for (int _u = 0; _u < 4; _u++) {                                           \
            int _seg = _u * 256 + tid;                                             \
            int _row = _seg >> 3, _q = _seg & 7;                                   \
            int _src = srow[_row];                                                 \
            const float* _ga = x + (size_t)_src * C_IN + _k0 + _q * 4;             \
            CP_ASYNC(_sa + (uint32_t)(_row * PIT + _q * 4) * 4u, _ga, 16);         \
        }                                                                          \
        _Pragma("unroll")                                                          \
        for (int _u = 0; _u < 4; _u++) {                                           \
            int _seg = _u * 256 + tid;                                             \
            int _n = _seg >> 3, _q = _seg & 7;                                     \
            const float* _gb = Bt + (size_t)(colStart + _n) * C_IN + _k0 + _q * 4; \
            CP_ASYNC(_sb + (uint32_t)(_n * PIT + _q * 4) * 4u, _gb, 16);           \
        }                                                                          \
        CP_COMMIT();                                                               \
    } while (0)

#define COMPUTE(c)                                                                 \
    do {                                                                           \
        const float* Ac = As + ((c) % 3) * ASTAGE;                                 \
        const float* Bc = Bs + ((c) % 3) * ASTAGE;                                 \
        _Pragma("unroll")                                                          \
        for (int kk = 0; kk < 4; kk++) {                                           \
            const int k8 = kk * 8;                                                 \
            uint32_t a[2][4];                                                      \
            _Pragma("unroll")                                                      \
            for (int i = 0; i < 2; i++) {                                          \
                const float* ap = Ac + (wm * 32 + i * 16 + (lane >> 2)) * PIT      \
                                  + k8 + (lane & 3);                               \
                a[i][0] = f2tf32(ap[0]);                                           \
                a[i][1] = f2tf32(ap[8 * PIT]);                                     \
                a[i][2] = f2tf32(ap[4]);                                           \
                a[i][3] = f2tf32(ap[8 * PIT + 4]);                                 \
            }                                                                      \
            _Pragma("unroll")                                                      \
            for (int j = 0; j < 8; j++) {                                          \
                const float* bp = Bc + (wn * 64 + j * 8 + (lane >> 2)) * PIT       \
                                  + k8 + (lane & 3);                               \
                uint32_t b0 = __float_as_uint(bp[0]);                              \
                uint32_t b1 = __float_as_uint(bp[4]);                              \
                MMA(acc[0][j], a[0], b0, b1);                                      \
                MMA(acc[1][j], a[1], b0, b1);                                      \
            }                                                                      \
        }                                                                          \
    } while (0)

    LOAD_CHUNK(0);
    LOAD_CHUNK(1);

    LOAD_CHUNK(2);
    CP_WAIT(2); __syncthreads();
    COMPUTE(0); __syncthreads();          // protects stage 0 before LOAD_CHUNK(3)

    LOAD_CHUNK(3);
    CP_WAIT(2); __syncthreads();
    COMPUTE(1);

    CP_WAIT(1); __syncthreads();
    COMPUTE(2);

    CP_WAIT(0); __syncthreads();
    COMPUTE(3);

    // ---- epilogue: fp16 stores at sequential perm positions (coalesced) ----
#pragma unroll
    for (int i = 0; i < 2; i++) {
#pragma unroll
        for (int j = 0; j < 8; j++) {
            int rp = p0 + wm * 32 + i * 16 + (lane >> 2);
            int cg = colStart + wn * 64 + j * 8 + (lane & 3) * 2;
            __half2 h01 = __floats2half2_rn(acc[i][j][0], acc[i][j][1]);
            __half2 h23 = __floats2half2_rn(acc[i][j][2], acc[i][j][3]);
            *(__half2*)&g_scratch[(size_t)rp * C_OUT + cg] = h01;
            *(__half2*)&g_scratch[(size_t)(rp + 8) * C_OUT + cg] = h23;
        }
    }
#undef LOAD_CHUNK
#undef COMPUTE
}

// ---------------- K_cstats: combine (discard) + per-channel stats, 2 sites in flight ----
#define SITES_PER_BLOCK 256
__global__ __launch_bounds__(256)
void k_cstats(int N) {
    __shared__ int   sp[SITES_PER_BLOCK * TAPS];   // 4 KB
    __shared__ float ssum[C_OUT], ssq[C_OUT];
    const int tid = threadIdx.x;
    const int s0  = blockIdx.x * SITES_PER_BLOCK;

    for (int i = tid; i < C_OUT; i += 256) { ssum[i] = 0.f; ssq[i] = 0.f; }
    for (int i = tid; i < SITES_PER_BLOCK * TAPS; i += 256) {
        int site = s0 + (i >> 2);
        sp[i] = (site < N) ? g_pslot[(size_t)site * TAPS + (i & 3)] : -1;
    }
    __syncthreads();

    const int c8 = tid & 31, sr = tid >> 5;
    float ls[8], lq[8];
#pragma unroll
    for (int c = 0; c < 8; c++) { ls[c] = 0.f; lq[c] = 0.f; }

    // two independent sites in flight per iteration (MLP x2)
#pragma unroll 2
    for (int it = 0; it < SITES_PER_BLOCK / 16; it++) {
        int slA = it * 16 + sr;
        int slB = slA + 8;
        float vA[8], vB[8];
#pragma unroll
        for (int c = 0; c < 8; c++) { vA[c] = 0.f; vB[c] = 0.f; }
#pragma unroll
        for (int t = 0; t < TAPS; t++) {
            int pA = sp[slA * 4 + t];
            int pB = sp[slB * 4 + t];
            if (pA >= 0) {
                float u[8];
                ld_scratch8(g_scratch + (size_t)pA * C_OUT + c8 * 8, u);
#pragma unroll
                for (int c = 0; c < 8; c++) vA[c] += u[c];
            }
            if (pB >= 0) {
                float u[8];
                ld_scratch8(g_scratch + (size_t)pB * C_OUT + c8 * 8, u);
#pragma unroll
                for (int c = 0; c < 8; c++) vB[c] += u[c];
            }
        }
#pragma unroll
        for (int c = 0; c < 8; c++) {
            ls[c] += vA[c] + vB[c];
            lq[c] += vA[c] * vA[c] + vB[c] * vB[c];
        }
    }
#pragma unroll
    for (int c = 0; c < 8; c++) {
        atomicAdd(&ssum[c8 * 8 + c], ls[c]);
        atomicAdd(&ssq[c8 * 8 + c], lq[c]);
    }
    __syncthreads();
    for (int i = tid; i < C_OUT; i += 256) {
        atomicAdd(&g_sum[i], ssum[i]);
        atomicAdd(&g_sumsq[i], ssq[i]);
    }
}

// ---------------- K_bn ----------------
__global__ void k_bn(const float* __restrict__ gamma, const float* __restrict__ beta) {
    int c = threadIdx.x;
    float cnt  = g_cnt;
    float mean = g_sum[c] / cnt;
    float var  = fmaxf(g_sumsq[c] / cnt - mean * mean, 0.f);
    float sc   = rsqrtf(var + BN_EPS) * gamma[c];
    float bi   = beta[c] - mean * sc;
    g_scale[c] = sc;
    g_bias[c]  = bi;
    g_sum[c]   = 0.f;
    g_sumsq[c] = 0.f;
    if (c == 0) g_cnt = 0.f;
    if (c < TAPS) g_tap_count[c] = 0;
}

// ---------------- K_final: recombine + BN + ReLU + mask -> y, 2 sites in flight --------
__global__ __launch_bounds__(256)
void k_final(float* __restrict__ y, const float* __restrict__ mask, int N) {
    __shared__ int sp[SITES_PER_BLOCK * TAPS];
    const int tid = threadIdx.x;
    const int s0  = blockIdx.x * SITES_PER_BLOCK;

    for (int i = tid; i < SITES_PER_BLOCK * TAPS; i += 256) {
        int site = s0 + (i >> 2);
        sp[i] = (site < N) ? g_pslot[(size_t)site * TAPS + (i & 3)] : -1;
    }
    __syncthreads();

    const int c8 = tid & 31, sr = tid >> 5;
    float sc[8], bi[8];
    *(float4*)&sc[0] = *(const float4*)&g_scale[c8 * 8];
    *(float4*)&sc[4] = *(const float4*)&g_scale[c8 * 8 + 4];
    *(float4*)&bi[0] = *(const float4*)&g_bias[c8 * 8];
    *(float4*)&bi[4] = *(const float4*)&g_bias[c8 * 8 + 4];

#pragma unroll 2
    for (int it = 0; it < SITES_PER_BLOCK / 16; it++) {
        int slA = it * 16 + sr;
        int slB = slA + 8;
        int siteA = s0 + slA, siteB = s0 + slB;
        float vA[8], vB[8];
#pragma unroll
        for (int c = 0; c < 8; c++) { vA[c] = 0.f; vB[c] = 0.f; }
#pragma unroll
        for (int t = 0; t < TAPS; t++) {
            int pA = sp[slA * 4 + t];
            int pB = sp[slB * 4 + t];
            if (pA >= 0) {
                float u[8];
                ld_scratch8(g_scratch + (size_t)pA * C_OUT + c8 * 8, u);
#pragma unroll
                for (int c = 0; c < 8; c++) vA[c] += u[c];
            }
            if (pB >= 0) {
                float u[8];
                ld_scratch8(g_scratch + (size_t)pB * C_OUT + c8 * 8, u);
#pragma unroll
                for (int c = 0; c < 8; c++) vB[c] += u[c];
            }
        }
        if (siteA < N) {
            float m = mask[siteA];
#pragma unroll
            for (int c = 0; c < 8; c++)
                vA[c] = fmaxf(fmaf(vA[c], sc[c], bi[c]), 0.f) * m;
            float4* o = (float4*)(y + (size_t)siteA * C_OUT + c8 * 8);
            o[0] = make_float4(vA[0], vA[1], vA[2], vA[3]);
            o[1] = make_float4(vA[4], vA[5], vA[6], vA[7]);
        }
        if (siteB < N) {
            float m = mask[siteB];
#pragma unroll
            for (int c = 0; c < 8; c++)
                vB[c] = fmaxf(fmaf(vB[c], sc[c], bi[c]), 0.f) * m;
            float4* o = (float4*)(y + (size_t)siteB * C_OUT + c8 * 8);
            o[0] = make_float4(vB[0], vB[1], vB[2], vB[3]);
            o[1] = make_float4(vB[4], vB[5], vB[6], vB[7]);
        }
    }
}

// ---------------- launch ----------------
extern "C" void kernel_launch(void* const* d_in, const int* in_sizes, int n_in,
                              void* d_out, int out_size) {
    const float* x         = (const float*)d_in[0];
    const float* W         = (const float*)d_in[1];
    const float* gamma     = (const float*)d_in[2];
    const float* beta      = (const float*)d_in[3];
    const int*   offset    = (const int*)d_in[4];
    const int*   out_index = (const int*)d_in[5];
    const float* mask      = (const float*)d_in[6];
    float*       out       = (float*)d_out;

    int N = in_sizes[4];
    if (N > N_MAX) N = N_MAX;

    cudaFuncSetAttribute(k_conv, cudaFuncAttributeMaxDynamicSharedMemorySize,
                         SMEM_BYTES);

    k_prep<<<256, 256>>>(W, offset, N);                                     // 0
    k_perm<<<256, 256>>>(offset, out_index, mask, N);                       // 1

    int tiles = (N + 127) / 128 + TAPS;   // upper bound incl. per-tap padding
    k_conv<<<dim3(2, tiles), 256, SMEM_BYTES>>>(x);                         // 2

    int cb = (N + SITES_PER_BLOCK - 1) / SITES_PER_BLOCK;
    k_cstats<<<cb, 256>>>(N);                                               // 3
    k_bn<<<1, 256>>>(gamma, beta);                                          // 4
    k_final<<<cb, 256>>>(out, mask, N);                                     // 5
}